// round 6
// baseline (speedup 1.0000x reference)
#include <cuda_runtime.h>
#include <cuda_bf16.h>
#include <cuda_fp16.h>
#include <cuda_fp8.h>
#include <cstdint>

#define B_ 65536
#define D_ 512
#define K_ 1024
#define C_ 100
#define TAU 16.0f

// ---------------- scratch (device globals; no allocations allowed) ----------------
__device__ __align__(16) __half    g_d2h[(size_t)B_ * K_];   // 128MB approx d2 (fp16)
__device__ __align__(16) uint8_t   g_Xf8[(size_t)B_ * D_];   // 32MB  X e4m3
__device__ __align__(16) uint8_t   g_Wf8[(size_t)K_ * D_];   // 512KB W^T e4m3
__device__ __align__(16) float     g_Wtf[(size_t)K_ * D_];   // 2MB   W^T fp32
__device__ float g_xsq[B_];
__device__ float g_wsq[K_];
__device__ int   g_assign[B_];
__device__ int   g_counts[K_];
__device__ int   g_offsets[K_];
__device__ int   g_cursor[K_];
__device__ int   g_order[B_];
__device__ float g_es[(size_t)K_ * D_];
__device__ int   g_bhist[K_ * C_];
__device__ float g_csnorm[K_];

__device__ __forceinline__ float GAM()  { return (float)0.99; }
__device__ __forceinline__ float OMG()  { return (float)(1.0 - 0.99); }
__device__ __forceinline__ float KEPS() { return (float)(1024 * 1e-5); }

// ---------------- PTX helpers (sm_89-era ISA; no tcgen05) ----------------
__device__ __forceinline__ uint32_t smem_u32(const void* p) {
    uint32_t a;
    asm("{ .reg .u64 t; cvta.to.shared.u64 t, %1; cvt.u32.u64 %0, t; }" : "=r"(a) : "l"(p));
    return a;
}
__device__ __forceinline__ void cp16(uint32_t s, const void* g) {
    asm volatile("cp.async.cg.shared.global [%0], [%1], 16;" :: "r"(s), "l"(g) : "memory");
}
#define CP_COMMIT() asm volatile("cp.async.commit_group;" ::: "memory")
#define CP_WAIT1()  asm volatile("cp.async.wait_group 1;" ::: "memory")
#define CP_WAIT0()  asm volatile("cp.async.wait_group 0;" ::: "memory")

__device__ __forceinline__ void ldm_x4(uint32_t& r0, uint32_t& r1, uint32_t& r2, uint32_t& r3, uint32_t a) {
    asm volatile("ldmatrix.sync.aligned.m8n8.x4.shared.b16 {%0,%1,%2,%3}, [%4];"
                 : "=r"(r0), "=r"(r1), "=r"(r2), "=r"(r3) : "r"(a));
}
// fp8 e4m3 MMA, k=32 per step; fragment byte-layout identical to bf16 m16n8k16 (b16 view)
__device__ __forceinline__ void mma16832(float* c, const uint32_t* a, const uint32_t* b) {
    asm volatile("mma.sync.aligned.m16n8k32.row.col.f32.e4m3.e4m3.f32 "
                 "{%0,%1,%2,%3}, {%4,%5,%6,%7}, {%8,%9}, {%0,%1,%2,%3};"
                 : "+f"(c[0]), "+f"(c[1]), "+f"(c[2]), "+f"(c[3])
                 : "r"(a[0]), "r"(a[1]), "r"(a[2]), "r"(a[3]), "r"(b[0]), "r"(b[1]));
}

// ---------------- init scratch ----------------
__global__ void k_init() {
    int i = blockIdx.x * blockDim.x + threadIdx.x;
    if (i < K_)       { g_counts[i] = 0; g_wsq[i] = 0.f; }
    if (i < K_ * C_)  g_bhist[i]  = 0;
}

// ---------------- X -> e4m3 + ||x||^2 (warp per row) ----------------
__global__ void k_xconv(const float* __restrict__ X) {
    int w = (blockIdx.x * blockDim.x + threadIdx.x) >> 5;
    int lane = threadIdx.x & 31;
    if (w >= B_) return;
    const float4* p = (const float4*)(X + (size_t)w * D_);
    uint32_t* dst = (uint32_t*)(g_Xf8 + (size_t)w * D_);
    float s = 0.f;
    #pragma unroll
    for (int j = 0; j < 4; ++j) {
        float4 v = p[lane + j * 32];
        s += v.x * v.x + v.y * v.y + v.z * v.z + v.w * v.w;
        __nv_fp8x2_storage_t lo = __nv_cvt_float2_to_fp8x2(make_float2(v.x, v.y), __NV_SATFINITE, __NV_E4M3);
        __nv_fp8x2_storage_t hi = __nv_cvt_float2_to_fp8x2(make_float2(v.z, v.w), __NV_SATFINITE, __NV_E4M3);
        dst[lane + j * 32] = (uint32_t)lo | ((uint32_t)hi << 16);
    }
    #pragma unroll
    for (int o = 16; o; o >>= 1) s += __shfl_xor_sync(0xFFFFFFFFu, s, o);
    if (lane == 0) g_xsq[w] = s;
}

// ---------------- W transpose (e4m3 + fp32) fused with ||w_k||^2 partials ----------------
__global__ void k_wt(const float* __restrict__ W) {
    __shared__ float tile[32][33];
    __shared__ float sq[32][33];
    int d0 = blockIdx.x * 32, k0 = blockIdx.y * 32;
    int tx = threadIdx.x, ty = threadIdx.y;
    float v0 = W[(size_t)(d0 + ty) * K_ + k0 + tx];
    tile[ty][tx] = v0;
    sq[ty][tx]   = v0 * v0;
    __syncthreads();
    #pragma unroll
    for (int o = 16; o; o >>= 1) {
        if (ty < o) sq[ty][tx] += sq[ty + o][tx];
        __syncthreads();
    }
    if (ty == 0) atomicAdd(&g_wsq[k0 + tx], sq[0][tx]);
    int k = k0 + ty, d = d0 + tx;
    float v = tile[tx][ty];
    g_Wtf[(size_t)k * D_ + d] = v;
    g_Wf8[(size_t)k * D_ + d] = (uint8_t)__nv_cvt_float_to_fp8(v, __NV_SATFINITE, __NV_E4M3);
}

// ---------------- fp8 MMA GEMM: d2h[b,k] = xsq - 2*x.w + wsq (fp16 out) ----------------
// Tile 128x128, BK=128 fp8 bytes, cp.async double buffer, pitch 144B conflict-free
#define PITCH 144
#define TBUF  18432   // 128 rows * 144 B
#define NKT   4       // 512 / 128

__global__ void __launch_bounds__(256, 2)
k_gemm_fp8() {
    extern __shared__ char dynsmem[];
    __shared__ float wsq_s[128];

    const int tid  = threadIdx.x;
    const int bn   = blockIdx.x, bm = blockIdx.y;
    const int wid  = tid >> 5, lane = tid & 31;
    const int wm   = wid & 3;      // 4 warps along M (32 rows each)
    const int wn   = wid >> 2;     // 2 warps along N (64 cols each)

    uint32_t sbase = smem_u32(dynsmem);
    const uint32_t Abuf[2] = { sbase,             sbase + TBUF };
    const uint32_t Bbuf[2] = { sbase + 2 * TBUF,  sbase + 3 * TBUF };

    if (tid < 128) wsq_s[tid] = g_wsq[bn * 128 + tid];

    const int r = tid >> 3;        // row 0..31 (+32*i)
    const int c = tid & 7;         // 16B chunk within 128B row

    auto issue = [&](int kt, int bf) {
        #pragma unroll
        for (int i = 0; i < 4; ++i) {
            int row = r + 32 * i;
            cp16(Abuf[bf] + row * PITCH + c * 16,
                 g_Xf8 + (size_t)(bm * 128 + row) * D_ + kt * 128 + c * 16);
            cp16(Bbuf[bf] + row * PITCH + c * 16,
                 g_Wf8 + (size_t)(bn * 128 + row) * D_ + kt * 128 + c * 16);
        }
    };

    issue(0, 0); CP_COMMIT();
    issue(1, 1); CP_COMMIT();

    float acc[2][8][4];
    #pragma unroll
    for (int mt = 0; mt < 2; ++mt)
        #pragma unroll
        for (int nt = 0; nt < 8; ++nt)
            #pragma unroll
            for (int q = 0; q < 4; ++q) acc[mt][nt][q] = 0.f;

    #pragma unroll 1
    for (int kt = 0; kt < NKT; ++kt) {
        if (kt < NKT - 1) CP_WAIT1(); else CP_WAIT0();
        __syncthreads();
        const uint32_t Ab = Abuf[kt & 1], Bb = Bbuf[kt & 1];

        #pragma unroll
        for (int ks = 0; ks < 4; ++ks) {    // 4 x k32 = 128 bytes
            uint32_t a[2][4];
            #pragma unroll
            for (int mt = 0; mt < 2; ++mt) {
                uint32_t addr = Ab + (uint32_t)((wm * 32 + mt * 16 + (lane & 15)) * PITCH
                                                + ks * 32 + (lane >> 4) * 16);
                ldm_x4(a[mt][0], a[mt][1], a[mt][2], a[mt][3], addr);
            }
            uint32_t b[8][2];
            #pragma unroll
            for (int np = 0; np < 4; ++np) {
                uint32_t nrow = wn * 64 + np * 16 + (lane & 7) + ((lane >> 4) << 3);
                uint32_t addr = Bb + nrow * PITCH + ks * 32 + (((lane >> 3) & 1) << 4);
                ldm_x4(b[2 * np][0], b[2 * np][1], b[2 * np + 1][0], b[2 * np + 1][1], addr);
            }
            #pragma unroll
            for (int mt = 0; mt < 2; ++mt)
                #pragma unroll
                for (int nt = 0; nt < 8; ++nt)
                    mma16832(acc[mt][nt], a[mt], b[nt]);
        }
        __syncthreads();
        if (kt + 2 < NKT) { issue(kt + 2, kt & 1); CP_COMMIT(); }
    }

    // epilogue: v = (xsq - 2*dot) + wsq  ->  fp16
    const int g = lane >> 2, th2 = (lane & 3) * 2;
    #pragma unroll
    for (int mt = 0; mt < 2; ++mt) {
        int row0 = bm * 128 + wm * 32 + mt * 16 + g;
        float xs0 = g_xsq[row0], xs1 = g_xsq[row0 + 8];
        __half* d0 = g_d2h + (size_t)row0 * K_ + bn * 128 + wn * 64;
        __half* d1 = d0 + (size_t)8 * K_;
        #pragma unroll
        for (int nt = 0; nt < 8; ++nt) {
            int col = wn * 64 + nt * 8 + th2;
            float w0 = wsq_s[col], w1 = wsq_s[col + 1];
            float v00 = (xs0 - 2.0f * acc[mt][nt][0]) + w0;
            float v01 = (xs0 - 2.0f * acc[mt][nt][1]) + w1;
            float v10 = (xs1 - 2.0f * acc[mt][nt][2]) + w0;
            float v11 = (xs1 - 2.0f * acc[mt][nt][3]) + w1;
            __half2 h0 = __floats2half2_rn(v00, v01);
            __half2 h1 = __floats2half2_rn(v10, v11);
            *(__half2*)(d0 + nt * 8 + th2) = h0;
            *(__half2*)(d1 + nt * 8 + th2) = h1;
        }
    }
}

// ---------------- argmin scan + exact fp32 rescore of near-ties ----------------
__global__ void k_argmin(const float* __restrict__ X, float* __restrict__ out_am) {
    __shared__ int s_cnt[8];
    __shared__ int s_list[8][128];
    int wid = threadIdx.x >> 5, lane = threadIdx.x & 31;
    int row = blockIdx.x * 8 + wid;

    const uint4* p = (const uint4*)(g_d2h + (size_t)row * K_);
    float vals[32];                 // vals[i*8+s] -> k = i*256 + lane*8 + s
    #pragma unroll
    for (int i = 0; i < 4; ++i) {
        uint4 v = p[i * 32 + lane];
        uint32_t u[4] = {v.x, v.y, v.z, v.w};
        #pragma unroll
        for (int q = 0; q < 4; ++q) {
            float2 f = __half22float2(*(__half2*)&u[q]);
            vals[i * 8 + q * 2 + 0] = fmaxf(f.x, 0.f);
            vals[i * 8 + q * 2 + 1] = fmaxf(f.y, 0.f);
        }
    }
    unsigned long long best = ~0ull;
    #pragma unroll
    for (int i = 0; i < 4; ++i)
        #pragma unroll
        for (int s = 0; s < 8; ++s) {
            int k = i * 256 + lane * 8 + s;
            unsigned long long pk =
                ((unsigned long long)__float_as_uint(vals[i * 8 + s]) << 32) | (unsigned)k;
            best = min(best, pk);
        }
    #pragma unroll
    for (int o = 16; o; o >>= 1) {
        unsigned long long other = __shfl_xor_sync(0xFFFFFFFFu, best, o);
        best = min(best, other);
    }
    float thr = __uint_as_float((unsigned)(best >> 32)) + TAU;
    int cct = 0;
    #pragma unroll
    for (int t = 0; t < 32; ++t) cct += (vals[t] <= thr);
    #pragma unroll
    for (int o = 16; o; o >>= 1) cct += __shfl_xor_sync(0xFFFFFFFFu, cct, o);

    int kfin;
    if (cct == 1) {
        kfin = (int)(best & 0xFFFFFFFFull);      // unique candidate == exact argmin
    } else {
        if (lane == 0) s_cnt[wid] = 0;
        __syncwarp();
        #pragma unroll
        for (int i = 0; i < 4; ++i)
            #pragma unroll
            for (int s = 0; s < 8; ++s)
                if (vals[i * 8 + s] <= thr) {
                    int pos = atomicAdd(&s_cnt[wid], 1);
                    if (pos < 128) s_list[wid][pos] = i * 256 + lane * 8 + s;
                }
        __syncwarp();
        int n = min(s_cnt[wid], 128);
        float xs = g_xsq[row];
        const float* xr = X + (size_t)row * D_;
        unsigned long long eb = ~0ull;
        for (int cc = 0; cc < n; ++cc) {
            int k = s_list[wid][cc];
            const float* wr = g_Wtf + (size_t)k * D_;
            float s = 0.f;
            #pragma unroll
            for (int j = 0; j < 16; ++j)
                s += xr[lane + j * 32] * wr[lane + j * 32];
            #pragma unroll
            for (int o = 16; o; o >>= 1) s += __shfl_xor_sync(0xFFFFFFFFu, s, o);
            float d2 = (xs - 2.0f * s) + g_wsq[k];
            float d  = __fsqrt_rn(fmaxf(d2, 0.0f));
            unsigned long long pk = ((unsigned long long)__float_as_uint(d) << 32) | (unsigned)k;
            eb = min(eb, pk);
        }
        kfin = (int)(eb & 0xFFFFFFFFull);
    }
    if (lane == 0) {
        g_assign[row] = kfin;
        out_am[row] = (float)kfin;
    }
}

// ---------------- counts + class histogram ----------------
__global__ void k_post(const int* __restrict__ keys) {
    int b = blockIdx.x * blockDim.x + threadIdx.x;
    if (b >= B_) return;
    int k = g_assign[b];
    atomicAdd(&g_counts[k], 1);
    atomicAdd(&g_bhist[k * C_ + keys[b]], 1);
}

// ---------------- cluster-size EMA, normalization, prefix scan ----------------
__global__ void k_stats(const float* __restrict__ cluster_size, float* __restrict__ out_ncs) {
    __shared__ float red[K_];
    __shared__ int   scan[K_];
    int t = threadIdx.x;
    int cnt = g_counts[t];
    float nidx = (cnt == 0) ? 1.0f : (float)cnt;
    float ncs = cluster_size[t] * GAM() + OMG() * nidx;
    out_ncs[t] = ncs;

    red[t] = ncs; __syncthreads();
    #pragma unroll
    for (int o = 512; o; o >>= 1) { if (t < o) red[t] += red[t + o]; __syncthreads(); }
    float n = red[0];
    g_csnorm[t] = ((ncs + 1e-5f) / (n + KEPS())) * n;

    scan[t] = cnt; __syncthreads();
    for (int o = 1; o < K_; o <<= 1) {
        int v = (t >= o) ? scan[t - o] : 0;
        __syncthreads();
        scan[t] += v;
        __syncthreads();
    }
    int excl = scan[t] - cnt;
    g_offsets[t] = excl;
    g_cursor[t]  = excl;
}

// ---------------- counting-sort scatter ----------------
__global__ void k_scatter() {
    int b = blockIdx.x * blockDim.x + threadIdx.x;
    if (b >= B_) return;
    int k = g_assign[b];
    int pos = atomicAdd(&g_cursor[k], 1);
    g_order[pos] = b;
}

// ---------------- per-cluster embed_sum (coalesced gather, MLP=4) ----------------
__global__ void k_embed(const float* __restrict__ X) {
    int k = blockIdx.x;
    int d = threadIdx.x;
    int start = g_offsets[k], cnt = g_counts[k];
    const int* ord = g_order + start;
    float a0 = 0.f, a1 = 0.f, a2 = 0.f, a3 = 0.f;
    int i = 0;
    for (; i + 4 <= cnt; i += 4) {
        int b0 = ord[i + 0], b1 = ord[i + 1], b2 = ord[i + 2], b3 = ord[i + 3];
        a0 += X[(size_t)b0 * D_ + d];
        a1 += X[(size_t)b1 * D_ + d];
        a2 += X[(size_t)b2 * D_ + d];
        a3 += X[(size_t)b3 * D_ + d];
    }
    for (; i < cnt; ++i) a0 += X[(size_t)ord[i] * D_ + d];
    g_es[(size_t)k * D_ + d] = (a0 + a1) + (a2 + a3);
}

// ---------------- embed_avg EMA + weight ----------------
__global__ void k_ema(const float* __restrict__ ea,
                      float* __restrict__ out_w, float* __restrict__ out_nea) {
    __shared__ float tile[32][33];
    int d0 = blockIdx.x * 32, k0 = blockIdx.y * 32;
    int tx = threadIdx.x, ty = threadIdx.y;
    tile[ty][tx] = g_es[(size_t)(k0 + ty) * D_ + d0 + tx];
    __syncthreads();
    int d = d0 + ty, k = k0 + tx;
    size_t idx = (size_t)d * K_ + k;
    float nea = ea[idx] * GAM() + OMG() * tile[tx][ty];
    out_nea[idx] = nea;
    out_w[idx]   = nea / g_csnorm[k];
}

// ---------------- hist EMA ----------------
__global__ void k_hist(const float* __restrict__ hist, float* __restrict__ out_h) {
    int i = blockIdx.x * blockDim.x + threadIdx.x;
    if (i < K_ * C_) out_h[i] = hist[i] * GAM() + OMG() * (float)g_bhist[i];
}

// ---------------- launch ----------------
extern "C" void kernel_launch(void* const* d_in, const int* in_sizes, int n_in,
                              void* d_out, int out_size) {
    const float* X    = (const float*)d_in[0];
    const int*   keys = (const int*)  d_in[1];
    const float* W    = (const float*)d_in[2];
    const float* cs   = (const float*)d_in[3];
    const float* ea   = (const float*)d_in[4];
    const float* hist = (const float*)d_in[5];

    float* out      = (float*)d_out;
    float* out_w    = out;
    float* out_ncs  = out + 524288;
    float* out_nea  = out + 525312;
    float* out_hist = out + 1049600;
    float* out_am   = out + 1152000;

    cudaFuncSetAttribute(k_gemm_fp8, cudaFuncAttributeMaxDynamicSharedMemorySize, 4 * TBUF);

    k_init<<<(K_ * C_ + 255) / 256, 256>>>();
    k_xconv<<<(B_ * 32) / 256, 256>>>(X);
    k_wt<<<dim3(D_ / 32, K_ / 32), dim3(32, 32)>>>(W);

    k_gemm_fp8<<<dim3(K_ / 128, B_ / 128), 256, 4 * TBUF>>>();

    k_argmin<<<B_ / 8, 256>>>(X, out_am);
    k_post<<<B_ / 256, 256>>>(keys);
    k_stats<<<1, K_>>>(cs, out_ncs);
    k_scatter<<<B_ / 256, 256>>>();
    k_embed<<<K_, D_>>>(X);
    k_ema<<<dim3(D_ / 32, K_ / 32), dim3(32, 32)>>>(ea, out_w, out_nea);
    k_hist<<<(K_ * C_ + 255) / 256, 256>>>(hist, out_hist);
}